// round 3
// baseline (speedup 1.0000x reference)
#include <cuda_runtime.h>
#include <cstdint>

// Per-row loss scratch (allocation-free: static device global).
#define MAX_B 16384
__device__ float g_row_loss[MAX_B];

__device__ __forceinline__ float stable_s(float x) {
    // s(x) = x+1 if x>=0 else 1/(1-x)   (exact fp32 division to match reference)
    return (x >= 0.0f) ? (x + 1.0f) : (1.0f / (1.0f - x));
}

__device__ __forceinline__ float warp_reduce(float v) {
    #pragma unroll
    for (int off = 16; off > 0; off >>= 1)
        v += __shfl_down_sync(0xFFFFFFFFu, v, off);
    return v;
}

__global__ void __launch_bounds__(512)
stablemax_row_kernel(const float* __restrict__ logits,
                     const int* __restrict__ targets,   // int32: JAX default x64-disabled
                     int C) {
    const int r = blockIdx.x;
    const float* __restrict__ row = logits + (size_t)r * (size_t)C;
    const int tid = threadIdx.x;
    const int nthr = blockDim.x;

    // ---- alignment head: rows are only 4B-aligned (C*4 % 16 == 4) ----
    uintptr_t addr = (uintptr_t)row;
    int head = ((16 - (int)(addr & 15)) & 15) >> 2;   // 0..3 floats to 16B align
    if (head > C) head = C;

    float acc0 = 0.0f, acc1 = 0.0f, acc2 = 0.0f, acc3 = 0.0f;
    if (tid < head) acc0 += stable_s(row[tid]);

    const int n_rem = C - head;
    const int n_vec = n_rem >> 2;                      // number of float4's
    const float4* __restrict__ vrow = (const float4*)(row + head);

    // ---- vector body: 4x unrolled, 4 independent accumulators for MLP ----
    int i = tid;
    for (; i + 3 * nthr < n_vec; i += 4 * nthr) {
        float4 a = vrow[i];
        float4 b = vrow[i + nthr];
        float4 c = vrow[i + 2 * nthr];
        float4 d = vrow[i + 3 * nthr];
        acc0 += stable_s(a.x) + stable_s(a.y) + stable_s(a.z) + stable_s(a.w);
        acc1 += stable_s(b.x) + stable_s(b.y) + stable_s(b.z) + stable_s(b.w);
        acc2 += stable_s(c.x) + stable_s(c.y) + stable_s(c.z) + stable_s(c.w);
        acc3 += stable_s(d.x) + stable_s(d.y) + stable_s(d.z) + stable_s(d.w);
    }
    for (; i < n_vec; i += nthr) {
        float4 a = vrow[i];
        acc0 += stable_s(a.x) + stable_s(a.y) + stable_s(a.z) + stable_s(a.w);
    }

    // ---- scalar tail ----
    const int tail_start = head + (n_vec << 2);
    const int tail = C - tail_start;
    if (tid < tail) acc0 += stable_s(row[tail_start + tid]);

    float local = (acc0 + acc1) + (acc2 + acc3);

    // ---- block reduction ----
    __shared__ float warp_sums[16];
    float wsum = warp_reduce(local);
    const int wid = tid >> 5, lid = tid & 31;
    if (lid == 0) warp_sums[wid] = wsum;
    __syncthreads();
    if (wid == 0) {
        const int nwarps = nthr >> 5;
        float v = (lid < nwarps) ? warp_sums[lid] : 0.0f;
        v = warp_reduce(v);
        if (lid == 0) {
            float denom = fmaxf(v, 1e-12f);
            int t = targets[r];
            if (t < 0) t = 0;
            if (t >= C) t = C - 1;                     // defensive clamp, no-op for valid data
            float s_t = stable_s(__ldg(row + t));
            float pt = s_t / denom;
            g_row_loss[r] = -logf(fmaxf(pt, 1e-12f));
        }
    }
}

__global__ void __launch_bounds__(1024)
stablemax_mean_kernel(float* __restrict__ out, int B) {
    const int tid = threadIdx.x;
    float local = 0.0f;
    for (int i = tid; i < B; i += 1024)
        local += g_row_loss[i];

    __shared__ float warp_sums[32];
    float wsum = warp_reduce(local);
    const int wid = tid >> 5, lid = tid & 31;
    if (lid == 0) warp_sums[wid] = wsum;
    __syncthreads();
    if (wid == 0) {
        float v = (lid < 32) ? warp_sums[lid] : 0.0f;
        v = warp_reduce(v);
        if (lid == 0) out[0] = v / (float)B;
    }
}

extern "C" void kernel_launch(void* const* d_in, const int* in_sizes, int n_in,
                              void* d_out, int out_size) {
    const float* logits = (const float*)d_in[0];
    const int* targets = (const int*)d_in[1];
    const int B = in_sizes[1];
    const int C = in_sizes[0] / B;

    stablemax_row_kernel<<<B, 512>>>(logits, targets, C);
    stablemax_mean_kernel<<<1, 1024>>>((float*)d_out, B);
}

// round 5
// speedup vs baseline: 1.2157x; 1.2157x over previous
#include <cuda_runtime.h>
#include <cstdint>

// Per-row loss scratch (allocation-free: static device global).
#define MAX_B 16384
__device__ float g_row_loss[MAX_B];

__device__ __forceinline__ float fast_rcp(float x) {
    float r;
    asm("rcp.approx.f32 %0, %1;" : "=f"(r) : "f"(x));
    return r;
}

__device__ __forceinline__ float stable_s(float x) {
    // s(x) = x+1 if x>=0 else 1/(1-x). approx rcp: <=1 ulp, fine for 1e-3 tol.
    return (x >= 0.0f) ? (x + 1.0f) : fast_rcp(1.0f - x);
}

__device__ __forceinline__ float warp_reduce(float v) {
    #pragma unroll
    for (int off = 16; off > 0; off >>= 1)
        v += __shfl_down_sync(0xFFFFFFFFu, v, off);
    return v;
}

template <int NTHR>
__global__ void __launch_bounds__(NTHR)
stablemax_row_kernel(const float* __restrict__ logits,
                     const int* __restrict__ targets,
                     int C) {
    const int r = blockIdx.x;
    const float* __restrict__ row = logits + (size_t)r * (size_t)C;
    const int tid = threadIdx.x;

    // ---- alignment head: rows are only 4B-aligned (C*4 % 16 == 4) ----
    uintptr_t addr = (uintptr_t)row;
    int head = ((16 - (int)(addr & 15)) & 15) >> 2;   // 0..3 floats to 16B align
    if (head > C) head = C;

    float acc0 = 0.0f, acc1 = 0.0f, acc2 = 0.0f, acc3 = 0.0f;
    if (tid < head) acc0 += stable_s(__ldcs(row + tid));

    const int n_rem = C - head;
    const int n_vec = n_rem >> 2;                      // number of float4's
    const float4* __restrict__ vrow = (const float4*)(row + head);

    // ---- vector body: 4x unrolled, 4 independent accumulators for MLP ----
    int i = tid;
    for (; i + 3 * NTHR < n_vec; i += 4 * NTHR) {
        float4 a = __ldcs(vrow + i);
        float4 b = __ldcs(vrow + i + NTHR);
        float4 c = __ldcs(vrow + i + 2 * NTHR);
        float4 d = __ldcs(vrow + i + 3 * NTHR);
        acc0 += stable_s(a.x) + stable_s(a.y) + stable_s(a.z) + stable_s(a.w);
        acc1 += stable_s(b.x) + stable_s(b.y) + stable_s(b.z) + stable_s(b.w);
        acc2 += stable_s(c.x) + stable_s(c.y) + stable_s(c.z) + stable_s(c.w);
        acc3 += stable_s(d.x) + stable_s(d.y) + stable_s(d.z) + stable_s(d.w);
    }
    for (; i < n_vec; i += NTHR) {
        float4 a = __ldcs(vrow + i);
        acc0 += stable_s(a.x) + stable_s(a.y) + stable_s(a.z) + stable_s(a.w);
    }

    // ---- scalar tail ----
    const int tail_start = head + (n_vec << 2);
    const int tail = C - tail_start;
    if (tid < tail) acc0 += stable_s(__ldcs(row + tail_start + tid));

    float local = (acc0 + acc1) + (acc2 + acc3);

    // ---- block reduction ----
    __shared__ float warp_sums[NTHR / 32];
    float wsum = warp_reduce(local);
    const int wid = tid >> 5, lid = tid & 31;
    if (lid == 0) warp_sums[wid] = wsum;
    __syncthreads();
    if (wid == 0) {
        float v = (lid < NTHR / 32) ? warp_sums[lid] : 0.0f;
        v = warp_reduce(v);
        if (lid == 0) {
            float denom = fmaxf(v, 1e-12f);
            int t = targets[r];
            if (t < 0) t = 0;
            if (t >= C) t = C - 1;                     // defensive clamp, no-op for valid data
            float s_t = stable_s(__ldg(row + t));
            float pt = s_t / denom;
            g_row_loss[r] = -logf(fmaxf(pt, 1e-12f));
        }
    }
}

__global__ void __launch_bounds__(1024)
stablemax_mean_kernel(float* __restrict__ out, int B) {
    const int tid = threadIdx.x;
    float local = 0.0f;
    for (int i = tid; i < B; i += 1024)
        local += g_row_loss[i];

    __shared__ float warp_sums[32];
    float wsum = warp_reduce(local);
    const int wid = tid >> 5, lid = tid & 31;
    if (lid == 0) warp_sums[wid] = wsum;
    __syncthreads();
    if (wid == 0) {
        float v = (lid < 32) ? warp_sums[lid] : 0.0f;
        v = warp_reduce(v);
        if (lid == 0) out[0] = v / (float)B;
    }
}

extern "C" void kernel_launch(void* const* d_in, const int* in_sizes, int n_in,
                              void* d_out, int out_size) {
    const float* logits = (const float*)d_in[0];
    const int* targets = (const int*)d_in[1];
    const int B = in_sizes[1];
    const int C = in_sizes[0] / B;

    stablemax_row_kernel<512><<<B, 512>>>(logits, targets, C);
    stablemax_mean_kernel<<<1, 1024>>>((float*)d_out, B);
}